// round 1
// baseline (speedup 1.0000x reference)
#include <cuda_runtime.h>

#define BATCH 4
#define S_LEN 2048
#define EMB   1024
#define NH    16
#define HD    64

// Scratch (allocation-free requirement -> __device__ globals)
static __device__ float g_kb[BATCH * NH * S_LEN * HD];   // K in [B,H,S,D]
static __device__ float g_qb[BATCH * NH * S_LEN * HD];   // Q in [B,H,S,D]
static __device__ float g_vb[BATCH * NH * S_LEN * HD];   // V in [B,H,S,D]
static __device__ float g_ob[BATCH * S_LEN * EMB];       // attention out in [B,S,E]

// ---------------------------------------------------------------------------
// Tiled fp32 SGEMM: C[M,N] = A[M,K] @ B[K,N] + bias[N]
// 128x128 block tile, BK=8, 256 threads, 8x8 per-thread microkernel.
// mode 0: plain row-major store to C.
// mode 1: scatter epilogue for the QKV projection -> g_kb/g_qb/g_vb in
//         [B,H,S,D] layout. Split order (per reference): k, q, v.
// ---------------------------------------------------------------------------
__global__ __launch_bounds__(256) void sgemm_kernel(
    const float* __restrict__ A, const float* __restrict__ B,
    const float* __restrict__ bias, float* __restrict__ C,
    int M, int N, int K, int mode,
    float* __restrict__ kb, float* __restrict__ qb, float* __restrict__ vb)
{
    __shared__ float As[8][128];   // transposed: As[k][m]
    __shared__ float Bs[8][128];   // Bs[k][n]

    const int tid = threadIdx.x;
    const int bm0 = blockIdx.y * 128;
    const int bn0 = blockIdx.x * 128;
    const int tr = tid >> 4;       // 0..15
    const int tc = tid & 15;       // 0..15

    // load mapping
    const int arow = tid >> 1;            // 0..127
    const int acol = (tid & 1) * 4;       // 0 or 4
    const int brow = tid >> 5;            // 0..7
    const int bcol = (tid & 31) * 4;      // 0..124

    const float* Ap = A + (size_t)(bm0 + arow) * K + acol;
    const float* Bp = B + (size_t)brow * N + bn0 + bcol;

    float acc[8][8];
#pragma unroll
    for (int i = 0; i < 8; i++)
#pragma unroll
        for (int j = 0; j < 8; j++) acc[i][j] = 0.f;

    for (int k0 = 0; k0 < K; k0 += 8) {
        float4 av = *(const float4*)(Ap + k0);
        float4 bv = *(const float4*)(Bp + (size_t)k0 * N);
        __syncthreads();
        As[acol + 0][arow] = av.x;
        As[acol + 1][arow] = av.y;
        As[acol + 2][arow] = av.z;
        As[acol + 3][arow] = av.w;
        *(float4*)&Bs[brow][bcol] = bv;
        __syncthreads();

#pragma unroll
        for (int kk = 0; kk < 8; kk++) {
            float a[8], b[8];
            *(float4*)&a[0] = *(const float4*)&As[kk][tr * 4];
            *(float4*)&a[4] = *(const float4*)&As[kk][64 + tr * 4];
            *(float4*)&b[0] = *(const float4*)&Bs[kk][tc * 4];
            *(float4*)&b[4] = *(const float4*)&Bs[kk][64 + tc * 4];
#pragma unroll
            for (int i = 0; i < 8; i++)
#pragma unroll
                for (int j = 0; j < 8; j++)
                    acc[i][j] = fmaf(a[i], b[j], acc[i][j]);
        }
    }

#pragma unroll
    for (int i = 0; i < 8; i++) {
        const int gm = bm0 + ((i < 4) ? (tr * 4 + i) : (64 + tr * 4 + i - 4));
#pragma unroll
        for (int jg = 0; jg < 2; jg++) {
            const int gn = bn0 + (jg ? 64 : 0) + tc * 4;
            float4 v;
            v.x = acc[i][jg * 4 + 0] + bias[gn + 0];
            v.y = acc[i][jg * 4 + 1] + bias[gn + 1];
            v.z = acc[i][jg * 4 + 2] + bias[gn + 2];
            v.w = acc[i][jg * 4 + 3] + bias[gn + 3];
            if (mode == 0) {
                *(float4*)&C[(size_t)gm * N + gn] = v;
            } else {
                // gn in [0,3072): section (k/q/v), head, dim
                const int sec = gn >> 10;
                const int h   = (gn >> 6) & 15;
                const int d   = gn & 63;
                const int b_  = gm >> 11;       // row / 2048
                const int s   = gm & 2047;
                float* dst = (sec == 0) ? kb : ((sec == 1) ? qb : vb);
                *(float4*)&dst[(((size_t)(b_ * NH + h)) * S_LEN + s) * HD + d] = v;
            }
        }
    }
}

// ---------------------------------------------------------------------------
// Flash attention (causal), fp32. One block per (64-row query tile, b*h).
// 256 threads, 4x4 per-thread microkernel for QK^T and P.V.
// Online softmax with 16-lane shuffle reductions.
// ---------------------------------------------------------------------------
#define AP 68  // shared pitch (floats): 68 % 4 == 0 (float4-aligned), odd bank step

__global__ __launch_bounds__(256) void attn_kernel(
    const float* __restrict__ qb, const float* __restrict__ kb,
    const float* __restrict__ vb, float* __restrict__ ob)
{
    extern __shared__ float sm[];
    float* Qs = sm;                  // [64][AP] transposed: Qs[d*AP + m]
    float* Ks = Qs + 64 * AP;        // [64][AP] transposed: Ks[d*AP + n]
    float* Vs = Ks + 64 * AP;        // [64][AP] natural:    Vs[c*AP + d]
    float* Ps = Vs + 64 * AP;        // [64][AP] transposed: Ps[c*AP + m]

    const int tid = threadIdx.x;
    const int qt = blockIdx.x;       // query tile
    const int bh = blockIdx.y;       // b*NH + h
    const int q0 = qt * 64;

    const float* Q  = qb + (size_t)bh * S_LEN * HD;
    const float* Kp = kb + (size_t)bh * S_LEN * HD;
    const float* Vp = vb + (size_t)bh * S_LEN * HD;

    // load Q tile, transposed into Qs[d][m]
#pragma unroll
    for (int rep = 0; rep < 4; rep++) {
        const int fid = tid + rep * 256;   // 0..1023 float4s
        const int row = fid >> 4;
        const int d   = (fid & 15) * 4;
        float4 v = *(const float4*)(Q + (size_t)(q0 + row) * HD + d);
        Qs[(d + 0) * AP + row] = v.x;
        Qs[(d + 1) * AP + row] = v.y;
        Qs[(d + 2) * AP + row] = v.z;
        Qs[(d + 3) * AP + row] = v.w;
    }

    const int tr = tid >> 4;   // 0..15 -> rows tr*4..tr*4+3
    const int tc = tid & 15;   // 0..15 -> cols tc*4..tc*4+3

    float m_i[4], l_i[4], o[4][4];
#pragma unroll
    for (int i = 0; i < 4; i++) {
        m_i[i] = -1e30f;
        l_i[i] = 0.f;
#pragma unroll
        for (int j = 0; j < 4; j++) o[i][j] = 0.f;
    }

    for (int kt = 0; kt <= qt; kt++) {
        const int k0 = kt * 64;
        __syncthreads();   // previous iteration's smem reads done (also orders Q load)

        // load K (transposed) and V (natural) tiles
#pragma unroll
        for (int rep = 0; rep < 4; rep++) {
            const int fid = tid + rep * 256;
            const int row = fid >> 4;
            const int d   = (fid & 15) * 4;
            float4 kv = *(const float4*)(Kp + (size_t)(k0 + row) * HD + d);
            Ks[(d + 0) * AP + row] = kv.x;
            Ks[(d + 1) * AP + row] = kv.y;
            Ks[(d + 2) * AP + row] = kv.z;
            Ks[(d + 3) * AP + row] = kv.w;
            float4 vv = *(const float4*)(Vp + (size_t)(k0 + row) * HD + d);
            *(float4*)&Vs[row * AP + d] = vv;
        }
        __syncthreads();

        // scores S = Q K^T (4x4 per thread)
        float s[4][4];
#pragma unroll
        for (int i = 0; i < 4; i++)
#pragma unroll
            for (int j = 0; j < 4; j++) s[i][j] = 0.f;

#pragma unroll 8
        for (int d = 0; d < 64; d++) {
            float4 q4 = *(const float4*)&Qs[d * AP + tr * 4];
            float4 k4 = *(const float4*)&Ks[d * AP + tc * 4];
            const float qa[4] = {q4.x, q4.y, q4.z, q4.w};
            const float ka[4] = {k4.x, k4.y, k4.z, k4.w};
#pragma unroll
            for (int i = 0; i < 4; i++)
#pragma unroll
                for (int j = 0; j < 4; j++)
                    s[i][j] = fmaf(qa[i], ka[j], s[i][j]);
        }

        const bool diag = (kt == qt);
        float p[4][4];
#pragma unroll
        for (int i = 0; i < 4; i++) {
            const int gq = q0 + tr * 4 + i;
            float rm = -1e30f;
#pragma unroll
            for (int j = 0; j < 4; j++) {
                float v = s[i][j] * 0.125f;          // 1/sqrt(64)
                if (diag && (k0 + tc * 4 + j) > gq) v = -1e30f;
                s[i][j] = v;
                rm = fmaxf(rm, v);
            }
            // max across the 16 threads owning this row (lanes form a 16-group)
            rm = fmaxf(rm, __shfl_xor_sync(0xffffffffu, rm, 1));
            rm = fmaxf(rm, __shfl_xor_sync(0xffffffffu, rm, 2));
            rm = fmaxf(rm, __shfl_xor_sync(0xffffffffu, rm, 4));
            rm = fmaxf(rm, __shfl_xor_sync(0xffffffffu, rm, 8));

            const float mnew = fmaxf(m_i[i], rm);
            const float f = __expf(m_i[i] - mnew);
            float rs = 0.f;
#pragma unroll
            for (int j = 0; j < 4; j++) {
                p[i][j] = __expf(s[i][j] - mnew);
                rs += p[i][j];
            }
            rs += __shfl_xor_sync(0xffffffffu, rs, 1);
            rs += __shfl_xor_sync(0xffffffffu, rs, 2);
            rs += __shfl_xor_sync(0xffffffffu, rs, 4);
            rs += __shfl_xor_sync(0xffffffffu, rs, 8);

            l_i[i] = l_i[i] * f + rs;
            m_i[i] = mnew;
#pragma unroll
            for (int j = 0; j < 4; j++) o[i][j] *= f;
        }

        // store P transposed: Ps[c][m]
#pragma unroll
        for (int i = 0; i < 4; i++)
#pragma unroll
            for (int j = 0; j < 4; j++)
                Ps[(tc * 4 + j) * AP + tr * 4 + i] = p[i][j];
        __syncthreads();

        // O += P @ V (4x4 per thread)
#pragma unroll 8
        for (int c = 0; c < 64; c++) {
            float4 p4 = *(const float4*)&Ps[c * AP + tr * 4];
            float4 v4 = *(const float4*)&Vs[c * AP + tc * 4];
            const float pa[4] = {p4.x, p4.y, p4.z, p4.w};
            const float va[4] = {v4.x, v4.y, v4.z, v4.w};
#pragma unroll
            for (int i = 0; i < 4; i++)
#pragma unroll
                for (int j = 0; j < 4; j++)
                    o[i][j] = fmaf(pa[i], va[j], o[i][j]);
        }
    }

    // epilogue: normalize and write [B,S,E]
    const int b = bh >> 4;
    const int h = bh & 15;
#pragma unroll
    for (int i = 0; i < 4; i++) {
        const float inv = 1.0f / l_i[i];
        const int gq = q0 + tr * 4 + i;
        float4 r;
        r.x = o[i][0] * inv;
        r.y = o[i][1] * inv;
        r.z = o[i][2] * inv;
        r.w = o[i][3] * inv;
        *(float4*)&ob[((size_t)b * S_LEN + gq) * EMB + h * HD + tc * 4] = r;
    }
}

// ---------------------------------------------------------------------------
// Launch
// ---------------------------------------------------------------------------
extern "C" void kernel_launch(void* const* d_in, const int* in_sizes, int n_in,
                              void* d_out, int out_size)
{
    const float* x      = (const float*)d_in[0];  // [4,2048,1024]
    const float* W_qkv  = (const float*)d_in[1];  // [1024,3072]
    const float* b_qkv  = (const float*)d_in[2];  // [3072]
    const float* W_proj = (const float*)d_in[3];  // [1024,1024]
    const float* b_proj = (const float*)d_in[4];  // [1024]
    float* out = (float*)d_out;                   // [4,2048,1024]

    float *kb, *qb, *vb, *ob;
    cudaGetSymbolAddress((void**)&kb, g_kb);
    cudaGetSymbolAddress((void**)&qb, g_qb);
    cudaGetSymbolAddress((void**)&vb, g_vb);
    cudaGetSymbolAddress((void**)&ob, g_ob);

    const int M = BATCH * S_LEN;  // 8192

    // 1) QKV projection + bias, scatter into per-head K/Q/V
    {
        dim3 grid(3 * EMB / 128, M / 128);  // (24, 64)
        sgemm_kernel<<<grid, 256>>>(x, W_qkv, b_qkv, nullptr,
                                    M, 3 * EMB, EMB, 1, kb, qb, vb);
    }

    // 2) fused causal flash attention
    {
        const int smem = 4 * 64 * AP * sizeof(float);  // 69632 bytes
        cudaFuncSetAttribute(attn_kernel,
                             cudaFuncAttributeMaxDynamicSharedMemorySize, smem);
        dim3 grid(S_LEN / 64, BATCH * NH);  // (32, 64)
        attn_kernel<<<grid, 256, smem>>>(qb, kb, vb, ob);
    }

    // 3) output projection + bias
    {
        dim3 grid(EMB / 128, M / 128);  // (8, 64)
        sgemm_kernel<<<grid, 256>>>(ob, W_proj, b_proj, out,
                                    M, EMB, EMB, 0,
                                    nullptr, nullptr, nullptr);
    }
}

// round 3
// speedup vs baseline: 1.4173x; 1.4173x over previous
#include <cuda_runtime.h>
#include <cuda_bf16.h>
#include <cstdint>

#define BATCH 4
#define S_LEN 2048
#define EMB   1024
#define NH    16
#define HD    64
#define MTOT  (BATCH * S_LEN)   // 8192

// ---------------------------------------------------------------------------
// Device-global scratch (allocation-free requirement)
// ---------------------------------------------------------------------------
static __device__ float g_kb[BATCH * NH * S_LEN * HD];   // K [B,H,S,D]
static __device__ float g_qb[BATCH * NH * S_LEN * HD];   // Q [B,H,S,D]
static __device__ float g_vb[BATCH * NH * S_LEN * HD];   // V [B,H,S,D]
static __device__ float g_ob[BATCH * S_LEN * EMB];       // attn out [B,S,E]

static __device__ __nv_bfloat16 g_Ah[MTOT * EMB];        // activation hi
static __device__ __nv_bfloat16 g_Al[MTOT * EMB];        // activation lo
static __device__ __nv_bfloat16 g_WhQ[3 * EMB * EMB];    // W_qkv^T hi  [N=3072,K=1024]
static __device__ __nv_bfloat16 g_WlQ[3 * EMB * EMB];    // W_qkv^T lo
static __device__ __nv_bfloat16 g_WhP[EMB * EMB];        // W_proj^T hi [N=1024,K=1024]
static __device__ __nv_bfloat16 g_WlP[EMB * EMB];        // W_proj^T lo

// ---------------------------------------------------------------------------
// Portable PTX helpers (compute_100-safe: mma.sync / ldmatrix / cp.async)
// ---------------------------------------------------------------------------
static __device__ __forceinline__ uint32_t smem_u32(const void* p) {
    uint32_t a;
    asm("{ .reg .u64 t; cvta.to.shared.u64 t, %1; cvt.u32.u64 %0, t; }" : "=r"(a) : "l"(p));
    return a;
}

static __device__ __forceinline__ void cp_async16(uint32_t dst, const void* src) {
    asm volatile("cp.async.cg.shared.global [%0], [%1], 16;" :: "r"(dst), "l"(src) : "memory");
}
#define CP_COMMIT() asm volatile("cp.async.commit_group;" ::: "memory")
#define CP_WAIT2()  asm volatile("cp.async.wait_group 2;" ::: "memory")
#define CP_WAIT0()  asm volatile("cp.async.wait_group 0;" ::: "memory")

static __device__ __forceinline__ void ldmatrix_x4(uint32_t* r, uint32_t addr) {
    asm volatile("ldmatrix.sync.aligned.m8n8.x4.shared.b16 {%0,%1,%2,%3}, [%4];"
                 : "=r"(r[0]), "=r"(r[1]), "=r"(r[2]), "=r"(r[3]) : "r"(addr));
}
static __device__ __forceinline__ void ldmatrix_x2(uint32_t* r, uint32_t addr) {
    asm volatile("ldmatrix.sync.aligned.m8n8.x2.shared.b16 {%0,%1}, [%2];"
                 : "=r"(r[0]), "=r"(r[1]) : "r"(addr));
}
static __device__ __forceinline__ void mma_bf16(float* d, const uint32_t* a, const uint32_t* b) {
    asm volatile("mma.sync.aligned.m16n8k16.row.col.f32.bf16.bf16.f32 "
                 "{%0,%1,%2,%3}, {%4,%5,%6,%7}, {%8,%9}, {%0,%1,%2,%3};"
                 : "+f"(d[0]), "+f"(d[1]), "+f"(d[2]), "+f"(d[3])
                 : "r"(a[0]), "r"(a[1]), "r"(a[2]), "r"(a[3]), "r"(b[0]), "r"(b[1]));
}

// ---------------------------------------------------------------------------
// Pre-processing kernels
// ---------------------------------------------------------------------------
__global__ void conv_act_kernel(const float4* __restrict__ in,
                                uint2* __restrict__ hi, uint2* __restrict__ lo, int n4)
{
    int i = blockIdx.x * 256 + threadIdx.x;
    if (i >= n4) return;
    float4 v = in[i];
    float a[4] = {v.x, v.y, v.z, v.w};
    uint32_t H[2] = {0, 0}, L[2] = {0, 0};
#pragma unroll
    for (int c = 0; c < 4; c++) {
        __nv_bfloat16 h = __float2bfloat16(a[c]);
        __nv_bfloat16 l = __float2bfloat16(a[c] - __bfloat162float(h));
        H[c >> 1] |= (uint32_t)__bfloat16_as_ushort(h) << ((c & 1) * 16);
        L[c >> 1] |= (uint32_t)__bfloat16_as_ushort(l) << ((c & 1) * 16);
    }
    hi[i] = make_uint2(H[0], H[1]);
    lo[i] = make_uint2(L[0], L[1]);
}

// W [K,N] fp32 -> W^T [N,K] bf16 hi/lo (tiled transpose)
__global__ void conv_wT_kernel(const float* __restrict__ W,
                               __nv_bfloat16* __restrict__ Th,
                               __nv_bfloat16* __restrict__ Tl, int Kd, int Nd)
{
    __shared__ float t[32][33];
    const int n0 = blockIdx.x * 32, k0 = blockIdx.y * 32;
    const int tx = threadIdx.x, ty = threadIdx.y;
#pragma unroll
    for (int j = 0; j < 32; j += 8)
        t[ty + j][tx] = W[(size_t)(k0 + ty + j) * Nd + n0 + tx];
    __syncthreads();
#pragma unroll
    for (int j = 0; j < 32; j += 8) {
        float v = t[tx][ty + j];
        __nv_bfloat16 h = __float2bfloat16(v);
        __nv_bfloat16 l = __float2bfloat16(v - __bfloat162float(h));
        size_t o = (size_t)(n0 + ty + j) * Kd + k0 + tx;
        Th[o] = h;
        Tl[o] = l;
    }
}

// ---------------------------------------------------------------------------
// bf16x3 mma.sync GEMM: C[M,N] = A[M,K] @ B^T (+bias)
// A hi/lo [M,K] K-major; B hi/lo [N,K] K-major.
// 128x128 CTA tile, 8 warps (64x32 each), BK=32, 3-stage cp.async pipeline.
// SMEM pitch 40 bf16 (80B): conflict-free ldmatrix, 16B-aligned cp.async.
// mode 0: row-major C.  mode 1: scatter to kb/qb/vb [B,H,S,D] (k,q,v order).
// ---------------------------------------------------------------------------
#define BK      32
#define PITCH   40                       // bf16 units
#define TILE_B  (128 * PITCH * 2)        // 10240 B per tile
#define STAGE_B (4 * TILE_B)             // Ah, Al, Bh, Bl = 40960 B
#define NSTAGE  3
#define GEMM_SMEM (NSTAGE * STAGE_B)     // 122880 B

static __device__ __forceinline__ void issue_stage(
    uint32_t sstage, const __nv_bfloat16* __restrict__ Ahg,
    const __nv_bfloat16* __restrict__ Alg, const __nv_bfloat16* __restrict__ Bhg,
    const __nv_bfloat16* __restrict__ Blg,
    int bm0, int bn0, int K, int kof, int tid)
{
    const int r = tid >> 2;           // 0..63
    const int c = tid & 3;            // 16B chunk (8 bf16)
#pragma unroll
    for (int rep = 0; rep < 2; rep++) {
        const int row = r + rep * 64;
        const uint32_t so = (uint32_t)(row * (PITCH * 2) + c * 16);
        const size_t ga = (size_t)(bm0 + row) * K + kof + c * 8;
        const size_t gb = (size_t)(bn0 + row) * K + kof + c * 8;
        cp_async16(sstage + 0 * TILE_B + so, Ahg + ga);
        cp_async16(sstage + 1 * TILE_B + so, Alg + ga);
        cp_async16(sstage + 2 * TILE_B + so, Bhg + gb);
        cp_async16(sstage + 3 * TILE_B + so, Blg + gb);
    }
}

__global__ __launch_bounds__(256, 1)
void gemm_bf16x3_kernel(
    const __nv_bfloat16* __restrict__ Ahg, const __nv_bfloat16* __restrict__ Alg,
    const __nv_bfloat16* __restrict__ Bhg, const __nv_bfloat16* __restrict__ Blg,
    const float* __restrict__ bias, float* __restrict__ C,
    int M, int N, int K, int mode,
    float* __restrict__ kb, float* __restrict__ qb, float* __restrict__ vb)
{
    extern __shared__ char smem[];
    const uint32_t sbase = smem_u32(smem);
    const int tid  = threadIdx.x;
    const int wid  = tid >> 5;
    const int lane = tid & 31;
    const int bm0 = blockIdx.y * 128;
    const int bn0 = blockIdx.x * 128;

    const int wm = (wid & 1) * 64;     // warp m offset in tile
    const int wn = (wid >> 1) * 32;    // warp n offset in tile

    float acc[4][4][4];
#pragma unroll
    for (int i = 0; i < 4; i++)
#pragma unroll
        for (int j = 0; j < 4; j++)
#pragma unroll
            for (int c = 0; c < 4; c++) acc[i][j][c] = 0.f;

    const int nk = K / BK;   // 32

    issue_stage(sbase + 0 * STAGE_B, Ahg, Alg, Bhg, Blg, bm0, bn0, K, 0, tid);
    CP_COMMIT();
    issue_stage(sbase + 1 * STAGE_B, Ahg, Alg, Bhg, Blg, bm0, bn0, K, BK, tid);
    CP_COMMIT();

    // precomputed ldmatrix lane addressing (byte offsets within a tile)
    const uint32_t a_row = (uint32_t)(lane & 15);
    const uint32_t a_koff = (uint32_t)((lane >> 4) * 16);
    const uint32_t b_row = (uint32_t)(lane & 7);
    const uint32_t b_koff = (uint32_t)(((lane >> 3) & 1) * 16);

    for (int it = 0; it < nk; it++) {
        if (it + 2 < nk)
            issue_stage(sbase + ((it + 2) % NSTAGE) * STAGE_B,
                        Ahg, Alg, Bhg, Blg, bm0, bn0, K, (it + 2) * BK, tid);
        CP_COMMIT();
        CP_WAIT2();
        __syncthreads();

        const uint32_t st = sbase + (it % NSTAGE) * STAGE_B;
#pragma unroll
        for (int ks = 0; ks < 2; ks++) {
            uint32_t ah[4][4], al[4][4], bh[4][2], bl[4][2];
#pragma unroll
            for (int i = 0; i < 4; i++) {
                const uint32_t ro = (uint32_t)((wm + i * 16) + a_row) * (PITCH * 2)
                                  + (uint32_t)(ks * 32) + a_koff;
                ldmatrix_x4(ah[i], st + 0 * TILE_B + ro);
                ldmatrix_x4(al[i], st + 1 * TILE_B + ro);
            }
#pragma unroll
            for (int j = 0; j < 4; j++) {
                const uint32_t ro = (uint32_t)((wn + j * 8) + b_row) * (PITCH * 2)
                                  + (uint32_t)(ks * 32) + b_koff;
                ldmatrix_x2(bh[j], st + 2 * TILE_B + ro);
                ldmatrix_x2(bl[j], st + 3 * TILE_B + ro);
            }
#pragma unroll
            for (int i = 0; i < 4; i++)
#pragma unroll
                for (int j = 0; j < 4; j++) {
                    mma_bf16(acc[i][j], ah[i], bh[j]);
                    mma_bf16(acc[i][j], ah[i], bl[j]);
                    mma_bf16(acc[i][j], al[i], bh[j]);
                }
        }
        __syncthreads();
    }

    // epilogue: fragment layout -> global
    const int lr = lane >> 2;          // 0..7
    const int lc = (lane & 3) * 2;     // 0,2,4,6
#pragma unroll
    for (int i = 0; i < 4; i++) {
#pragma unroll
        for (int j = 0; j < 4; j++) {
            const int col = bn0 + wn + j * 8 + lc;
            const float bx = bias[col], by = bias[col + 1];
#pragma unroll
            for (int h2 = 0; h2 < 2; h2++) {
                const int row = bm0 + wm + i * 16 + lr + h2 * 8;
                float2 v;
                v.x = acc[i][j][h2 * 2 + 0] + bx;
                v.y = acc[i][j][h2 * 2 + 1] + by;
                if (mode == 0) {
                    *(float2*)&C[(size_t)row * N + col] = v;
                } else {
                    const int sec = col >> 10;
                    const int hh  = (col >> 6) & 15;
                    const int d   = col & 63;
                    const int b_  = row >> 11;
                    const int s   = row & 2047;
                    float* dst = (sec == 0) ? kb : ((sec == 1) ? qb : vb);
                    *(float2*)&dst[(((size_t)(b_ * NH + hh)) * S_LEN + s) * HD + d] = v;
                }
            }
        }
    }
}

// ---------------------------------------------------------------------------
// Flash attention (causal), fp32 SIMT — unchanged (known passing)
// ---------------------------------------------------------------------------
#define AP 68

__global__ __launch_bounds__(256) void attn_kernel(
    const float* __restrict__ qb, const float* __restrict__ kb,
    const float* __restrict__ vb, float* __restrict__ ob)
{
    extern __shared__ float sm[];
    float* Qs = sm;
    float* Ks = Qs + 64 * AP;
    float* Vs = Ks + 64 * AP;
    float* Ps = Vs + 64 * AP;

    const int tid = threadIdx.x;
    const int qt = blockIdx.x;
    const int bh = blockIdx.y;
    const int q0 = qt * 64;

    const float* Q  = qb + (size_t)bh * S_LEN * HD;
    const float* Kp = kb + (size_t)bh * S_LEN * HD;
    const float* Vp = vb + (size_t)bh * S_LEN * HD;

#pragma unroll
    for (int rep = 0; rep < 4; rep++) {
        const int fid = tid + rep * 256;
        const int row = fid >> 4;
        const int d   = (fid & 15) * 4;
        float4 v = *(const float4*)(Q + (size_t)(q0 + row) * HD + d);
        Qs[(d + 0) * AP + row] = v.x;
        Qs[(d + 1) * AP + row] = v.y;
        Qs[(d + 2) * AP + row] = v.z;
        Qs[(d + 3) * AP + row] = v.w;
    }

    const int tr = tid >> 4;
    const int tc = tid & 15;

    float m_i[4], l_i[4], o[4][4];
#pragma unroll
    for (int i = 0; i < 4; i++) {
        m_i[i] = -1e30f;
        l_i[i] = 0.f;
#pragma unroll
        for (int j = 0; j < 4; j++) o[i][j] = 0.f;
    }

    for (int kt = 0; kt <= qt; kt++) {
        const int k0 = kt * 64;
        __syncthreads();

#pragma unroll
        for (int rep = 0; rep < 4; rep++) {
            const int fid = tid + rep * 256;
            const int row = fid >> 4;
            const int d   = (fid & 15) * 4;
            float4 kv = *(const float4*)(Kp + (size_t)(k0 + row) * HD + d);
            Ks[(d + 0) * AP + row] = kv.x;
            Ks[(d + 1) * AP + row] = kv.y;
            Ks[(d + 2) * AP + row] = kv.z;
            Ks[(d + 3) * AP + row] = kv.w;
            float4 vv = *(const float4*)(Vp + (size_t)(k0 + row) * HD + d);
            *(float4*)&Vs[row * AP + d] = vv;
        }
        __syncthreads();

        float s[4][4];
#pragma unroll
        for (int i = 0; i < 4; i++)
#pragma unroll
            for (int j = 0; j < 4; j++) s[i][j] = 0.f;

#pragma unroll 8
        for (int d = 0; d < 64; d++) {
            float4 q4 = *(const float4*)&Qs[d * AP + tr * 4];
            float4 k4 = *(const float4*)&Ks[d * AP + tc * 4];
            const float qa[4] = {q4.x, q4.y, q4.z, q4.w};
            const float ka[4] = {k4.x, k4.y, k4.z, k4.w};
#pragma unroll
            for (int i = 0; i < 4; i++)
#pragma unroll
                for (int j = 0; j < 4; j++)
                    s[i][j] = fmaf(qa[i], ka[j], s[i][j]);
        }

        const bool diag = (kt == qt);
        float p[4][4];
#pragma unroll
        for (int i = 0; i < 4; i++) {
            const int gq = q0 + tr * 4 + i;
            float rm = -1e30f;
#pragma unroll
            for (int j = 0; j < 4; j++) {
                float v = s[i][j] * 0.125f;
                if (diag && (k0 + tc * 4 + j) > gq) v = -1e30f;
                s[i][j] = v;
                rm = fmaxf(rm, v);
            }
            rm = fmaxf(rm, __shfl_xor_sync(0xffffffffu, rm, 1));
            rm = fmaxf(rm, __shfl_xor_sync(0xffffffffu, rm, 2));
            rm = fmaxf(rm, __shfl_xor_sync(0xffffffffu, rm, 4));
            rm = fmaxf(rm, __shfl_xor_sync(0xffffffffu, rm, 8));

            const float mnew = fmaxf(m_i[i], rm);
            const float f = __expf(m_i[i] - mnew);
            float rs = 0.f;
#pragma unroll
            for (int j = 0; j < 4; j++) {
                p[i][j] = __expf(s[i][j] - mnew);
                rs += p[i][j];
            }
            rs += __shfl_xor_sync(0xffffffffu, rs, 1);
            rs += __shfl_xor_sync(0xffffffffu, rs, 2);
            rs += __shfl_xor_sync(0xffffffffu, rs, 4);
            rs += __shfl_xor_sync(0xffffffffu, rs, 8);

            l_i[i] = l_i[i] * f + rs;
            m_i[i] = mnew;
#pragma unroll
            for (int j = 0; j < 4; j++) o[i][j] *= f;
        }

#pragma unroll
        for (int i = 0; i < 4; i++)
#pragma unroll
            for (int j = 0; j < 4; j++)
                Ps[(tc * 4 + j) * AP + tr * 4 + i] = p[i][j];
        __syncthreads();

#pragma unroll 8
        for (int c = 0; c < 64; c++) {
            float4 p4 = *(const float4*)&Ps[c * AP + tr * 4];
            float4 v4 = *(const float4*)&Vs[c * AP + tc * 4];
            const float pa[4] = {p4.x, p4.y, p4.z, p4.w};
            const float va[4] = {v4.x, v4.y, v4.z, v4.w};
#pragma unroll
            for (int i = 0; i < 4; i++)
#pragma unroll
                for (int j = 0; j < 4; j++)
                    o[i][j] = fmaf(pa[i], va[j], o[i][j]);
        }
    }

    const int b = bh >> 4;
    const int h = bh & 15;
#pragma unroll
    for (int i = 0; i < 4; i++) {
        const float inv = 1.0f / l_i[i];
        const int gq = q0 + tr * 4 + i;
        float4 r;
        r.x = o[i][0] * inv;
        r.y = o[i][1] * inv;
        r.z = o[i][2] * inv;
        r.w = o[i][3] * inv;
        *(float4*)&ob[((size_t)b * S_LEN + gq) * EMB + h * HD + tc * 4] = r;
    }
}

// ---------------------------------------------------------------------------
// Launch
// ---------------------------------------------------------------------------
extern "C" void kernel_launch(void* const* d_in, const int* in_sizes, int n_in,
                              void* d_out, int out_size)
{
    const float* x      = (const float*)d_in[0];
    const float* W_qkv  = (const float*)d_in[1];
    const float* b_qkv  = (const float*)d_in[2];
    const float* W_proj = (const float*)d_in[3];
    const float* b_proj = (const float*)d_in[4];
    float* out = (float*)d_out;

    float *kb, *qb, *vb, *ob;
    __nv_bfloat16 *Ah, *Al, *WhQ, *WlQ, *WhP, *WlP;
    cudaGetSymbolAddress((void**)&kb, g_kb);
    cudaGetSymbolAddress((void**)&qb, g_qb);
    cudaGetSymbolAddress((void**)&vb, g_vb);
    cudaGetSymbolAddress((void**)&ob, g_ob);
    cudaGetSymbolAddress((void**)&Ah, g_Ah);
    cudaGetSymbolAddress((void**)&Al, g_Al);
    cudaGetSymbolAddress((void**)&WhQ, g_WhQ);
    cudaGetSymbolAddress((void**)&WlQ, g_WlQ);
    cudaGetSymbolAddress((void**)&WhP, g_WhP);
    cudaGetSymbolAddress((void**)&WlP, g_WlP);

    cudaFuncSetAttribute(gemm_bf16x3_kernel,
                         cudaFuncAttributeMaxDynamicSharedMemorySize, GEMM_SMEM);

    // 0) pre-split weights (transposed) and activations
    {
        dim3 blk(32, 8);
        conv_wT_kernel<<<dim3(3 * EMB / 32, EMB / 32), blk>>>(W_qkv, WhQ, WlQ, EMB, 3 * EMB);
        conv_wT_kernel<<<dim3(EMB / 32, EMB / 32), blk>>>(W_proj, WhP, WlP, EMB, EMB);
        const int n4 = MTOT * EMB / 4;
        conv_act_kernel<<<n4 / 256, 256>>>((const float4*)x, (uint2*)Ah, (uint2*)Al, n4);
    }

    // 1) QKV projection (bf16x3 mma.sync) + bias, scatter into K/Q/V [B,H,S,D]
    gemm_bf16x3_kernel<<<dim3(3 * EMB / 128, MTOT / 128), 256, GEMM_SMEM>>>(
        Ah, Al, WhQ, WlQ, b_qkv, nullptr, MTOT, 3 * EMB, EMB, 1, kb, qb, vb);

    // 2) fused causal flash attention (fp32)
    {
        const int smem = 4 * 64 * AP * sizeof(float);
        cudaFuncSetAttribute(attn_kernel,
                             cudaFuncAttributeMaxDynamicSharedMemorySize, smem);
        attn_kernel<<<dim3(S_LEN / 64, BATCH * NH), 256, smem>>>(qb, kb, vb, ob);
    }

    // 3) split attention output, then output projection (bf16x3 mma.sync)
    {
        const int n4 = MTOT * EMB / 4;
        conv_act_kernel<<<n4 / 256, 256>>>((const float4*)ob, (uint2*)Ah, (uint2*)Al, n4);
        gemm_bf16x3_kernel<<<dim3(EMB / 128, MTOT / 128), 256, GEMM_SMEM>>>(
            Ah, Al, WhP, WlP, b_proj, out, MTOT, EMB, EMB, 0,
            nullptr, nullptr, nullptr);
    }
}

// round 4
// speedup vs baseline: 2.5658x; 1.8103x over previous
#include <cuda_runtime.h>
#include <cuda_bf16.h>
#include <cstdint>

#define BATCH 4
#define S_LEN 2048
#define EMB   1024
#define NH    16
#define HD    64
#define MTOT  (BATCH * S_LEN)   // 8192

// ---------------------------------------------------------------------------
// Device-global scratch (allocation-free requirement)
// ---------------------------------------------------------------------------
static __device__ __nv_bfloat16 g_Ah[MTOT * EMB];        // GEMM A hi (x split, then attn out)
static __device__ __nv_bfloat16 g_Al[MTOT * EMB];        // GEMM A lo
static __device__ __nv_bfloat16 g_WhQ[3 * EMB * EMB];    // W_qkv^T hi  [N=3072,K=1024]
static __device__ __nv_bfloat16 g_WlQ[3 * EMB * EMB];
static __device__ __nv_bfloat16 g_WhP[EMB * EMB];        // W_proj^T hi [N=1024,K=1024]
static __device__ __nv_bfloat16 g_WlP[EMB * EMB];

static __device__ __nv_bfloat16 g_Qh[BATCH * NH * S_LEN * HD];  // Q hi (pre-scaled)
static __device__ __nv_bfloat16 g_Ql[BATCH * NH * S_LEN * HD];
static __device__ __nv_bfloat16 g_Kh[BATCH * NH * S_LEN * HD];
static __device__ __nv_bfloat16 g_Kl[BATCH * NH * S_LEN * HD];
static __device__ __nv_bfloat16 g_Vh[BATCH * NH * S_LEN * HD];
static __device__ __nv_bfloat16 g_Vl[BATCH * NH * S_LEN * HD];

// ---------------------------------------------------------------------------
// Portable PTX helpers (compute_100-safe)
// ---------------------------------------------------------------------------
static __device__ __forceinline__ uint32_t smem_u32(const void* p) {
    uint32_t a;
    asm("{ .reg .u64 t; cvta.to.shared.u64 t, %1; cvt.u32.u64 %0, t; }" : "=r"(a) : "l"(p));
    return a;
}
static __device__ __forceinline__ void cp_async16(uint32_t dst, const void* src) {
    asm volatile("cp.async.cg.shared.global [%0], [%1], 16;" :: "r"(dst), "l"(src) : "memory");
}
#define CP_COMMIT() asm volatile("cp.async.commit_group;" ::: "memory")
#define CP_WAIT1()  asm volatile("cp.async.wait_group 1;" ::: "memory")

static __device__ __forceinline__ void ldmatrix_x4(uint32_t* r, uint32_t addr) {
    asm volatile("ldmatrix.sync.aligned.m8n8.x4.shared.b16 {%0,%1,%2,%3}, [%4];"
                 : "=r"(r[0]), "=r"(r[1]), "=r"(r[2]), "=r"(r[3]) : "r"(addr));
}
static __device__ __forceinline__ void ldmatrix_x2(uint32_t* r, uint32_t addr) {
    asm volatile("ldmatrix.sync.aligned.m8n8.x2.shared.b16 {%0,%1}, [%2];"
                 : "=r"(r[0]), "=r"(r[1]) : "r"(addr));
}
static __device__ __forceinline__ void ldmatrix_x2_trans(uint32_t* r, uint32_t addr) {
    asm volatile("ldmatrix.sync.aligned.m8n8.x2.trans.shared.b16 {%0,%1}, [%2];"
                 : "=r"(r[0]), "=r"(r[1]) : "r"(addr));
}
static __device__ __forceinline__ void mma_bf16(float* d, const uint32_t* a, const uint32_t* b) {
    asm volatile("mma.sync.aligned.m16n8k16.row.col.f32.bf16.bf16.f32 "
                 "{%0,%1,%2,%3}, {%4,%5,%6,%7}, {%8,%9}, {%0,%1,%2,%3};"
                 : "+f"(d[0]), "+f"(d[1]), "+f"(d[2]), "+f"(d[3])
                 : "r"(a[0]), "r"(a[1]), "r"(a[2]), "r"(a[3]), "r"(b[0]), "r"(b[1]));
}
static __device__ __forceinline__ float ex2f(float x) {
    float y;
    asm("ex2.approx.ftz.f32 %0, %1;" : "=f"(y) : "f"(x));
    return y;
}

// ---------------------------------------------------------------------------
// Pre-processing kernels
// ---------------------------------------------------------------------------
__global__ void conv_act_kernel(const float4* __restrict__ in,
                                uint2* __restrict__ hi, uint2* __restrict__ lo, int n4)
{
    int i = blockIdx.x * 256 + threadIdx.x;
    if (i >= n4) return;
    float4 v = in[i];
    float a[4] = {v.x, v.y, v.z, v.w};
    uint32_t H[2] = {0, 0}, L[2] = {0, 0};
#pragma unroll
    for (int c = 0; c < 4; c++) {
        __nv_bfloat16 h = __float2bfloat16(a[c]);
        __nv_bfloat16 l = __float2bfloat16(a[c] - __bfloat162float(h));
        H[c >> 1] |= (uint32_t)__bfloat16_as_ushort(h) << ((c & 1) * 16);
        L[c >> 1] |= (uint32_t)__bfloat16_as_ushort(l) << ((c & 1) * 16);
    }
    hi[i] = make_uint2(H[0], H[1]);
    lo[i] = make_uint2(L[0], L[1]);
}

__global__ void conv_wT_kernel(const float* __restrict__ W,
                               __nv_bfloat16* __restrict__ Th,
                               __nv_bfloat16* __restrict__ Tl, int Kd, int Nd)
{
    __shared__ float t[32][33];
    const int n0 = blockIdx.x * 32, k0 = blockIdx.y * 32;
    const int tx = threadIdx.x, ty = threadIdx.y;
#pragma unroll
    for (int j = 0; j < 32; j += 8)
        t[ty + j][tx] = W[(size_t)(k0 + ty + j) * Nd + n0 + tx];
    __syncthreads();
#pragma unroll
    for (int j = 0; j < 32; j += 8) {
        float v = t[tx][ty + j];
        __nv_bfloat16 h = __float2bfloat16(v);
        __nv_bfloat16 l = __float2bfloat16(v - __bfloat162float(h));
        size_t o = (size_t)(n0 + ty + j) * Kd + k0 + tx;
        Th[o] = h;
        Tl[o] = l;
    }
}

// ---------------------------------------------------------------------------
// bf16x3 mma.sync GEMM, 128x128 tile, 8 warps (64x32), BK=32, 2-stage pipeline.
// 2 CTAs/SM. mode 0: fp32 C (+bias). mode 1: QKV epilogue -> hi/lo bf16
// K/Q/V in [B,H,S,D]; Q pre-scaled by 0.125*log2(e).
// ---------------------------------------------------------------------------
#define BK      32
#define PITCH   40
#define TILE_B  (128 * PITCH * 2)        // 10240 B
#define STAGE_B (4 * TILE_B)             // 40960 B
#define GEMM_SMEM (2 * STAGE_B)          // 81920 B

#define QSCALE  0.1803368801111244f      // 0.125 * log2(e)

static __device__ __forceinline__ void issue_stage(
    uint32_t sstage, const __nv_bfloat16* __restrict__ Ahg,
    const __nv_bfloat16* __restrict__ Alg, const __nv_bfloat16* __restrict__ Bhg,
    const __nv_bfloat16* __restrict__ Blg,
    int bm0, int bn0, int K, int kof, int tid)
{
    const int r = tid >> 2;
    const int c = tid & 3;
#pragma unroll
    for (int rep = 0; rep < 2; rep++) {
        const int row = r + rep * 64;
        const uint32_t so = (uint32_t)(row * (PITCH * 2) + c * 16);
        const size_t ga = (size_t)(bm0 + row) * K + kof + c * 8;
        const size_t gb = (size_t)(bn0 + row) * K + kof + c * 8;
        cp_async16(sstage + 0 * TILE_B + so, Ahg + ga);
        cp_async16(sstage + 1 * TILE_B + so, Alg + ga);
        cp_async16(sstage + 2 * TILE_B + so, Bhg + gb);
        cp_async16(sstage + 3 * TILE_B + so, Blg + gb);
    }
}

__global__ __launch_bounds__(256, 2)
void gemm_bf16x3_kernel(
    const __nv_bfloat16* __restrict__ Ahg, const __nv_bfloat16* __restrict__ Alg,
    const __nv_bfloat16* __restrict__ Bhg, const __nv_bfloat16* __restrict__ Blg,
    const float* __restrict__ bias, float* __restrict__ C,
    int M, int N, int K, int mode,
    __nv_bfloat16* __restrict__ kh, __nv_bfloat16* __restrict__ kl,
    __nv_bfloat16* __restrict__ qh, __nv_bfloat16* __restrict__ ql,
    __nv_bfloat16* __restrict__ vh, __nv_bfloat16* __restrict__ vl)
{
    extern __shared__ char smem[];
    const uint32_t sbase = smem_u32(smem);
    const int tid  = threadIdx.x;
    const int wid  = tid >> 5;
    const int lane = tid & 31;
    const int bm0 = blockIdx.y * 128;
    const int bn0 = blockIdx.x * 128;

    const int wm = (wid & 1) * 64;
    const int wn = (wid >> 1) * 32;

    float acc[4][4][4];
#pragma unroll
    for (int i = 0; i < 4; i++)
#pragma unroll
        for (int j = 0; j < 4; j++)
#pragma unroll
            for (int c = 0; c < 4; c++) acc[i][j][c] = 0.f;

    const int nk = K / BK;

    issue_stage(sbase + 0 * STAGE_B, Ahg, Alg, Bhg, Blg, bm0, bn0, K, 0, tid);
    CP_COMMIT();
    issue_stage(sbase + 1 * STAGE_B, Ahg, Alg, Bhg, Blg, bm0, bn0, K, BK, tid);
    CP_COMMIT();

    const uint32_t a_row = (uint32_t)(lane & 15);
    const uint32_t a_koff = (uint32_t)((lane >> 4) * 16);
    const uint32_t b_row = (uint32_t)(lane & 7);
    const uint32_t b_koff = (uint32_t)(((lane >> 3) & 1) * 16);

    for (int it = 0; it < nk; it++) {
        CP_WAIT1();
        __syncthreads();
        const uint32_t st = sbase + (it & 1) * STAGE_B;
#pragma unroll
        for (int ks = 0; ks < 2; ks++) {
            uint32_t ah[4][4], al[4][4];
#pragma unroll
            for (int i = 0; i < 4; i++) {
                const uint32_t ro = (uint32_t)((wm + i * 16) + a_row) * (PITCH * 2)
                                  + (uint32_t)(ks * 32) + a_koff;
                ldmatrix_x4(ah[i], st + 0 * TILE_B + ro);
                ldmatrix_x4(al[i], st + 1 * TILE_B + ro);
            }
#pragma unroll
            for (int j = 0; j < 4; j++) {
                uint32_t bh2[2], bl2[2];
                const uint32_t ro = (uint32_t)((wn + j * 8) + b_row) * (PITCH * 2)
                                  + (uint32_t)(ks * 32) + b_koff;
                ldmatrix_x2(bh2, st + 2 * TILE_B + ro);
                ldmatrix_x2(bl2, st + 3 * TILE_B + ro);
#pragma unroll
                for (int i = 0; i < 4; i++) {
                    mma_bf16(acc[i][j], ah[i], bh2);
                    mma_bf16(acc[i][j], ah[i], bl2);
                    mma_bf16(acc[i][j], al[i], bh2);
                }
            }
        }
        __syncthreads();
        if (it + 2 < nk)
            issue_stage(st, Ahg, Alg, Bhg, Blg, bm0, bn0, K, (it + 2) * BK, tid);
        CP_COMMIT();
    }

    const int lr = lane >> 2;
    const int lc = (lane & 3) * 2;
#pragma unroll
    for (int i = 0; i < 4; i++) {
#pragma unroll
        for (int j = 0; j < 4; j++) {
            const int col = bn0 + wn + j * 8 + lc;
            const float bx = bias[col], by = bias[col + 1];
#pragma unroll
            for (int h2 = 0; h2 < 2; h2++) {
                const int row = bm0 + wm + i * 16 + lr + h2 * 8;
                float vx = acc[i][j][h2 * 2 + 0] + bx;
                float vy = acc[i][j][h2 * 2 + 1] + by;
                if (mode == 0) {
                    float2 v = make_float2(vx, vy);
                    *(float2*)&C[(size_t)row * N + col] = v;
                } else {
                    const int sec = col >> 10;
                    if (sec == 1) { vx *= QSCALE; vy *= QSCALE; }
                    const int hh  = (col >> 6) & 15;
                    const int d   = col & 63;
                    const int b_  = row >> 11;
                    const int s   = row & 2047;
                    const size_t off = (((size_t)(b_ * NH + hh)) * S_LEN + s) * HD + d;
                    __nv_bfloat16 hx = __float2bfloat16(vx);
                    __nv_bfloat16 hy = __float2bfloat16(vy);
                    __nv_bfloat16 lx = __float2bfloat16(vx - __bfloat162float(hx));
                    __nv_bfloat16 ly = __float2bfloat16(vy - __bfloat162float(hy));
                    __nv_bfloat16* dh = (sec == 0) ? kh : ((sec == 1) ? qh : vh);
                    __nv_bfloat16* dl = (sec == 0) ? kl : ((sec == 1) ? ql : vl);
                    __nv_bfloat162 hv; hv.x = hx; hv.y = hy;
                    __nv_bfloat162 lv; lv.x = lx; lv.y = ly;
                    *(__nv_bfloat162*)&dh[off] = hv;
                    *(__nv_bfloat162*)&dl[off] = lv;
                }
            }
        }
    }
}

// ---------------------------------------------------------------------------
// Flash attention (causal) on mma.sync, bf16x3 precision.
// Block: 128 q-rows x (B*H). 8 warps, each warp m16 x n64.
// K/V tiles of 64 keys, double-buffered cp.async.
// Output written as hi/lo bf16 into the proj GEMM input buffers.
// ---------------------------------------------------------------------------
#define KPITCH 144                       // bytes per 64-dim row (72 bf16)
#define QT (128 * KPITCH)                // 18432 B per Q component
#define CT (64 * KPITCH)                 // 9216 B per KV component tile
#define ATT_SMEM (2 * QT + 2 * 4 * CT)   // 110592 B

static __device__ __forceinline__ void issue_kv(
    uint32_t dst, const __nv_bfloat16* __restrict__ Kh, const __nv_bfloat16* __restrict__ Kl,
    const __nv_bfloat16* __restrict__ Vh, const __nv_bfloat16* __restrict__ Vl,
    size_t gbase, int k0, int tid)
{
    const int r = tid >> 2;
    const int c = tid & 3;
    const size_t g = gbase + (size_t)(k0 + r) * HD;
#pragma unroll
    for (int cc = 0; cc < 2; cc++) {
        const int ch = c + cc * 4;
        const uint32_t so = (uint32_t)(r * KPITCH + ch * 16);
        cp_async16(dst + 0 * CT + so, Kh + g + ch * 8);
        cp_async16(dst + 1 * CT + so, Kl + g + ch * 8);
        cp_async16(dst + 2 * CT + so, Vh + g + ch * 8);
        cp_async16(dst + 3 * CT + so, Vl + g + ch * 8);
    }
}

__global__ __launch_bounds__(256)
void attn_mma_kernel(
    const __nv_bfloat16* __restrict__ Qh, const __nv_bfloat16* __restrict__ Ql,
    const __nv_bfloat16* __restrict__ Kh, const __nv_bfloat16* __restrict__ Kl,
    const __nv_bfloat16* __restrict__ Vh, const __nv_bfloat16* __restrict__ Vl,
    __nv_bfloat16* __restrict__ Oh, __nv_bfloat16* __restrict__ Ol)
{
    extern __shared__ char smem[];
    const uint32_t sb = smem_u32(smem);
    const uint32_t sQ = sb;                  // Qh tile, Ql at +QT
    const uint32_t sKV = sb + 2 * QT;        // stages of 4*CT

    const int tid = threadIdx.x;
    const int lane = tid & 31;
    const int w = tid >> 5;
    const int qb = (int)gridDim.x - 1 - (int)blockIdx.x;   // long blocks first
    const int bh = blockIdx.y;
    const int q0 = qb * 128;
    const size_t base = (size_t)bh * S_LEN * HD;

    // load Q hi/lo tile (group G0)
    {
        const int r = tid >> 1;
        const int c0 = (tid & 1) * 4;
#pragma unroll
        for (int c = c0; c < c0 + 4; c++) {
            const uint32_t so = (uint32_t)(r * KPITCH + c * 16);
            const size_t g = base + (size_t)(q0 + r) * HD + c * 8;
            cp_async16(sQ + so, Qh + g);
            cp_async16(sQ + QT + so, Ql + g);
        }
    }
    CP_COMMIT();

    const int nt = 2 * qb + 2;
    issue_kv(sKV, Kh, Kl, Vh, Vl, base, 0, tid);   // G1 = kv tile 0
    CP_COMMIT();

    CP_WAIT1();          // G0 (Q) done
    __syncthreads();

    // resident Q fragments
    const int wm = w * 16;
    uint32_t qfh[4][4], qfl[4][4];
    {
        const uint32_t ab = sQ + (uint32_t)((wm + (lane & 15)) * KPITCH + (lane >> 4) * 16);
#pragma unroll
        for (int kk = 0; kk < 4; kk++) {
            ldmatrix_x4(qfh[kk], ab + kk * 32);
            ldmatrix_x4(qfl[kk], ab + QT + kk * 32);
        }
    }

    float o[8][4];
#pragma unroll
    for (int j = 0; j < 8; j++)
#pragma unroll
        for (int c = 0; c < 4; c++) o[j][c] = 0.f;
    float m0 = -1e30f, m1 = -1e30f, l0 = 0.f, l1 = 0.f;

    for (int it = 0; it < nt; it++) {
        if (it + 1 < nt) {
            issue_kv(sKV + ((it + 1) & 1) * 4 * CT, Kh, Kl, Vh, Vl, base, (it + 1) * 64, tid);
        }
        CP_COMMIT();
        CP_WAIT1();
        __syncthreads();

        const int k0 = it * 64;
        const bool active = (k0 <= q0 + wm + 15);
        if (active) {
            const uint32_t st = sKV + (it & 1) * 4 * CT;

            // ---- S = Q K^T (bf16x3), per warp m16 x n64 ----
            float s[8][4];
#pragma unroll
            for (int j = 0; j < 8; j++)
#pragma unroll
                for (int c = 0; c < 4; c++) s[j][c] = 0.f;

            const uint32_t kb_ = st + (uint32_t)((lane & 7) * KPITCH + ((lane >> 3) & 1) * 16);
#pragma unroll
            for (int kk = 0; kk < 4; kk++) {
#pragma unroll
                for (int j = 0; j < 8; j++) {
                    uint32_t bh2[2], bl2[2];
                    const uint32_t ro = kb_ + (uint32_t)(j * 8 * KPITCH + kk * 32);
                    ldmatrix_x2(bh2, ro);
                    ldmatrix_x2(bl2, ro + CT);
                    mma_bf16(s[j], qfh[kk], bh2);
                    mma_bf16(s[j], qfh[kk], bl2);
                    mma_bf16(s[j], qfl[kk], bh2);
                }
            }

            // ---- causal mask (scores already in log2 domain via Q scaling) ----
            if (k0 + 63 > q0 + wm) {
#pragma unroll
                for (int j = 0; j < 8; j++)
#pragma unroll
                    for (int c = 0; c < 4; c++) {
                        const int kc = k0 + j * 8 + 2 * (lane & 3) + (c & 1);
                        const int rq = q0 + wm + (lane >> 2) + (c >> 1) * 8;
                        if (kc > rq) s[j][c] = -1e30f;
                    }
            }

            // ---- online softmax (exp2 domain) ----
            float mx0 = -1e30f, mx1 = -1e30f;
#pragma unroll
            for (int j = 0; j < 8; j++) {
                mx0 = fmaxf(mx0, fmaxf(s[j][0], s[j][1]));
                mx1 = fmaxf(mx1, fmaxf(s[j][2], s[j][3]));
            }
            mx0 = fmaxf(mx0, __shfl_xor_sync(0xffffffffu, mx0, 1));
            mx0 = fmaxf(mx0, __shfl_xor_sync(0xffffffffu, mx0, 2));
            mx1 = fmaxf(mx1, __shfl_xor_sync(0xffffffffu, mx1, 1));
            mx1 = fmaxf(mx1, __shfl_xor_sync(0xffffffffu, mx1, 2));

            const float mn0 = fmaxf(m0, mx0);
            const float mn1 = fmaxf(m1, mx1);
            const float f0 = ex2f(m0 - mn0);
            const float f1 = ex2f(m1 - mn1);
            m0 = mn0; m1 = mn1;

            float sum0 = 0.f, sum1 = 0.f;
#pragma unroll
            for (int j = 0; j < 8; j++) {
                s[j][0] = ex2f(s[j][0] - mn0);
                s[j][1] = ex2f(s[j][1] - mn0);
                s[j][2] = ex2f(s[j][2] - mn1);
                s[j][3] = ex2f(s[j][3] - mn1);
                sum0 += s[j][0] + s[j][1];
                sum1 += s[j][2] + s[j][3];
            }
            sum0 += __shfl_xor_sync(0xffffffffu, sum0, 1);
            sum0 += __shfl_xor_sync(0xffffffffu, sum0, 2);
            sum1 += __shfl_xor_sync(0xffffffffu, sum1, 1);
            sum1 += __shfl_xor_sync(0xffffffffu, sum1, 2);
            l0 = l0 * f0 + sum0;
            l1 = l1 * f1 + sum1;

#pragma unroll
            for (int j = 0; j < 8; j++) {
                o[j][0] *= f0; o[j][1] *= f0;
                o[j][2] *= f1; o[j][3] *= f1;
            }

            // ---- O += P V (bf16x3), P from fragments ----
            const uint32_t vb_ = st + 2 * CT + (uint32_t)((lane & 15) * KPITCH);
#pragma unroll
            for (int t = 0; t < 4; t++) {
                uint32_t ph[4], pl[4];
#pragma unroll
                for (int half = 0; half < 2; half++) {
                    const float* sp = s[2 * t + half];
                    __nv_bfloat162 h01 = __float22bfloat162_rn(make_float2(sp[0], sp[1]));
                    __nv_bfloat162 h23 = __float22bfloat162_rn(make_float2(sp[2], sp[3]));
                    __nv_bfloat162 r01 = __float22bfloat162_rn(make_float2(
                        sp[0] - __bfloat162float(h01.x), sp[1] - __bfloat162float(h01.y)));
                    __nv_bfloat162 r23 = __float22bfloat162_rn(make_float2(
                        sp[2] - __bfloat162float(h23.x), sp[3] - __bfloat162float(h23.y)));
                    ph[2 * half + 0] = *(uint32_t*)&h01;
                    ph[2 * half + 1] = *(uint32_t*)&h23;
                    pl[2 * half + 0] = *(uint32_t*)&r01;
                    pl[2 * half + 1] = *(uint32_t*)&r23;
                }
                // reorder: a = {(lr,k),(lr+8,k),(lr,k+8),(lr+8,k+8)}
                uint32_t pa_h[4] = {ph[0], ph[1], ph[2], ph[3]};
                uint32_t pa_l[4] = {pl[0], pl[1], pl[2], pl[3]};
#pragma unroll
                for (int jd = 0; jd < 8; jd++) {
                    uint32_t vh2[2], vl2[2];
                    const uint32_t vo = vb_ + (uint32_t)(16 * t * KPITCH + jd * 16);
                    ldmatrix_x2_trans(vh2, vo);
                    ldmatrix_x2_trans(vl2, vo + CT);
                    mma_bf16(o[jd], pa_h, vh2);
                    mma_bf16(o[jd], pa_h, vl2);
                    mma_bf16(o[jd], pa_l, vh2);
                }
            }
        }
        __syncthreads();
    }

    // ---- epilogue: normalize, split hi/lo, write [M,E] bf16 ----
    const int b = bh >> 4;
    const int h = bh & 15;
    const float inv0 = 1.0f / l0;
    const float inv1 = 1.0f / l1;
    const int r0 = b * S_LEN + q0 + wm + (lane >> 2);
    const int colb = h * HD + 2 * (lane & 3);
#pragma unroll
    for (int jd = 0; jd < 8; jd++) {
        const int col = colb + jd * 8;
#pragma unroll
        for (int h2 = 0; h2 < 2; h2++) {
            const float inv = h2 ? inv1 : inv0;
            const float vx = o[jd][h2 * 2 + 0] * inv;
            const float vy = o[jd][h2 * 2 + 1] * inv;
            const size_t off = (size_t)(r0 + h2 * 8) * EMB + col;
            __nv_bfloat162 hv = __float22bfloat162_rn(make_float2(vx, vy));
            __nv_bfloat162 lv = __float22bfloat162_rn(make_float2(
                vx - __bfloat162float(hv.x), vy - __bfloat162float(hv.y)));
            *(__nv_bfloat162*)&Oh[off] = hv;
            *(__nv_bfloat162*)&Ol[off] = lv;
        }
    }
}

// ---------------------------------------------------------------------------
// Launch
// ---------------------------------------------------------------------------
extern "C" void kernel_launch(void* const* d_in, const int* in_sizes, int n_in,
                              void* d_out, int out_size)
{
    const float* x      = (const float*)d_in[0];
    const float* W_qkv  = (const float*)d_in[1];
    const float* b_qkv  = (const float*)d_in[2];
    const float* W_proj = (const float*)d_in[3];
    const float* b_proj = (const float*)d_in[4];
    float* out = (float*)d_out;

    __nv_bfloat16 *Ah, *Al, *WhQ, *WlQ, *WhP, *WlP;
    __nv_bfloat16 *Qh, *Ql, *Kh, *Kl, *Vh, *Vl;
    cudaGetSymbolAddress((void**)&Ah, g_Ah);
    cudaGetSymbolAddress((void**)&Al, g_Al);
    cudaGetSymbolAddress((void**)&WhQ, g_WhQ);
    cudaGetSymbolAddress((void**)&WlQ, g_WlQ);
    cudaGetSymbolAddress((void**)&WhP, g_WhP);
    cudaGetSymbolAddress((void**)&WlP, g_WlP);
    cudaGetSymbolAddress((void**)&Qh, g_Qh);
    cudaGetSymbolAddress((void**)&Ql, g_Ql);
    cudaGetSymbolAddress((void**)&Kh, g_Kh);
    cudaGetSymbolAddress((void**)&Kl, g_Kl);
    cudaGetSymbolAddress((void**)&Vh, g_Vh);
    cudaGetSymbolAddress((void**)&Vl, g_Vl);

    cudaFuncSetAttribute(gemm_bf16x3_kernel,
                         cudaFuncAttributeMaxDynamicSharedMemorySize, GEMM_SMEM);
    cudaFuncSetAttribute(attn_mma_kernel,
                         cudaFuncAttributeMaxDynamicSharedMemorySize, ATT_SMEM);

    // 0) pre-split weights (transposed) and input activations
    {
        dim3 blk(32, 8);
        conv_wT_kernel<<<dim3(3 * EMB / 32, EMB / 32), blk>>>(W_qkv, WhQ, WlQ, EMB, 3 * EMB);
        conv_wT_kernel<<<dim3(EMB / 32, EMB / 32), blk>>>(W_proj, WhP, WlP, EMB, EMB);
        const int n4 = MTOT * EMB / 4;
        conv_act_kernel<<<n4 / 256, 256>>>((const float4*)x, (uint2*)Ah, (uint2*)Al, n4);
    }

    // 1) QKV projection -> hi/lo bf16 K/Q/V in [B,H,S,D] (Q pre-scaled)
    gemm_bf16x3_kernel<<<dim3(3 * EMB / 128, MTOT / 128), 256, GEMM_SMEM>>>(
        Ah, Al, WhQ, WlQ, b_qkv, nullptr, MTOT, 3 * EMB, EMB, 1,
        Kh, Kl, Qh, Ql, Vh, Vl);

    // 2) fused causal flash attention (tensor cores, bf16x3) -> Ah/Al
    attn_mma_kernel<<<dim3(S_LEN / 128, BATCH * NH), 256, ATT_SMEM>>>(
        Qh, Ql, Kh, Kl, Vh, Vl, Ah, Al);

    // 3) output projection -> fp32 out
    gemm_bf16x3_kernel<<<dim3(EMB / 128, MTOT / 128), 256, GEMM_SMEM>>>(
        Ah, Al, WhP, WlP, b_proj, out, MTOT, EMB, EMB, 0,
        nullptr, nullptr, nullptr, nullptr, nullptr, nullptr);
}